// round 12
// baseline (speedup 1.0000x reference)
#include <cuda_runtime.h>
#include <cuda_bf16.h>
#include <math.h>

// Problem constants (fixed by the reference)
#define BATCH     65536
#define EMBED_DIM 128
#define NEG_K     5

#define WARPS_PER_BLOCK 4
#define BLOCK_THREADS   (WARPS_PER_BLOCK * 32)                 // 128
#define ELEMS_PER_WARP  2
#define NUM_BLOCKS      (BATCH / (WARPS_PER_BLOCK * ELEMS_PER_WARP))  // 8192
#define NUM_WARPS_TOTAL (BATCH / ELEMS_PER_WARP)               // 32768 arrivals

// Fixed-point packed accumulator+counter: low 48 bits = sum of
// round(warp_sum * 2^24) [loss >= 0; total*2^24 ~ 4.6e12 << 2^48],
// bits [48:63] = warp arrival count (32768 max, fits 16-bit field).
// Integer adds are associative -> deterministic regardless of arrival order;
// the warp whose returned old value carries count NUM_WARPS_TOTAL-1 holds the
// complete total after adding its own contribution. No fences, no smem, no
// __syncthreads, no second atomic.
#define Q_SCALE     16777216.0            // 2^24
#define INV_Q_SCALE (1.0 / 16777216.0)
#define COUNT_SHIFT 48
#define COUNT_ONE   (1ULL << COUNT_SHIFT)
#define SUM_MASK    ((1ULL << COUNT_SHIFT) - 1ULL)

__device__ unsigned long long g_packed = 0ULL;

__device__ __forceinline__ float log_sigmoid(float x) {
    // stable: min(x,0) - log1p(exp(-|x|))
    return fminf(x, 0.0f) - log1pf(__expf(-fabsf(x)));
}

__device__ __forceinline__ float dot4(float4 a, float4 b) {
    return a.x * b.x + a.y * b.y + a.z * b.z + a.w * b.w;
}

__global__ __launch_bounds__(BLOCK_THREADS, 5)   // regs ~56-63: 14 live float4, no spills
void skipgram_loss_kernel(const int* __restrict__ center,
                          const int* __restrict__ context,
                          const int* __restrict__ negatives,
                          const float* __restrict__ u_weight,
                          const float* __restrict__ v_weight,
                          float* __restrict__ out) {
    const int warp_in_block = threadIdx.x >> 5;
    const int lane          = threadIdx.x & 31;
    const int wg            = blockIdx.x * WARPS_PER_BLOCK + warp_in_block;
    const int b0            = wg * ELEMS_PER_WARP;   // even -> negatives base is 8B-aligned

    // ---- gather indices for both elements (vectorized negatives: 5x int2) ----
    const int ci0 = center[b0],  ci1 = center[b0 + 1];
    const int xi0 = context[b0], xi1 = context[b0 + 1];
    const int2* nv = reinterpret_cast<const int2*>(negatives + (size_t)b0 * NEG_K);
    int2 q0 = __ldg(nv + 0), q1 = __ldg(nv + 1), q2 = __ldg(nv + 2),
         q3 = __ldg(nv + 3), q4 = __ldg(nv + 4);
    const int n0[NEG_K] = { q0.x, q0.y, q1.x, q1.y, q2.x };
    const int n1[NEG_K] = { q2.y, q3.x, q3.y, q4.x, q4.y };

    // ---- issue all 14 row loads back-to-back (MLP=14 per lane) ----
    float4 c40 = __ldg(reinterpret_cast<const float4*>(u_weight + (size_t)ci0 * EMBED_DIM) + lane);
    float4 c41 = __ldg(reinterpret_cast<const float4*>(u_weight + (size_t)ci1 * EMBED_DIM) + lane);
    float4 x40 = __ldg(reinterpret_cast<const float4*>(v_weight + (size_t)xi0 * EMBED_DIM) + lane);
    float4 x41 = __ldg(reinterpret_cast<const float4*>(v_weight + (size_t)xi1 * EMBED_DIM) + lane);
    float4 n40[NEG_K], n41[NEG_K];
#pragma unroll
    for (int k = 0; k < NEG_K; k++)
        n40[k] = __ldg(reinterpret_cast<const float4*>(v_weight + (size_t)n0[k] * EMBED_DIM) + lane);
#pragma unroll
    for (int k = 0; k < NEG_K; k++)
        n41[k] = __ldg(reinterpret_cast<const float4*>(v_weight + (size_t)n1[k] * EMBED_DIM) + lane);

    // ---- 12 partial dot products per lane ----
    float acc0[1 + NEG_K], acc1[1 + NEG_K];
    acc0[0] = dot4(c40, x40);
    acc1[0] = dot4(c41, x41);
#pragma unroll
    for (int k = 0; k < NEG_K; k++) {
        acc0[1 + k] = dot4(c40, n40[k]);
        acc1[1 + k] = dot4(c41, n41[k]);
    }

    // ---- butterfly warp reduction of all 12 dots (ILP across accumulators) ----
    // Afterwards EVERY lane holds all 12 complete dot products.
#pragma unroll
    for (int off = 16; off > 0; off >>= 1) {
#pragma unroll
        for (int j = 0; j < 1 + NEG_K; j++) {
            acc0[j] += __shfl_xor_sync(0xFFFFFFFFu, acc0[j], off);
            acc1[j] += __shfl_xor_sync(0xFFFFFFFFu, acc1[j], off);
        }
    }

    // ---- convergent epilogue: all lanes compute both losses (no divergence,
    //      two independent 6-deep log-sigmoid chains interleave with ILP) ----
    float nl0 = 0.0f, nl1 = 0.0f;
#pragma unroll
    for (int k = 0; k < NEG_K; k++) {
        nl0 += log_sigmoid(-acc0[1 + k]);
        nl1 += log_sigmoid(-acc1[1 + k]);
    }
    const float l = -(log_sigmoid(acc0[0]) + nl0) - (log_sigmoid(acc1[0]) + nl1);

    // ---- per-WARP packed atomic: no smem, no __syncthreads, no serial tail ----
    if (lane == 0) {
        unsigned long long q = (unsigned long long)__double2ll_rn((double)l * Q_SCALE);
        unsigned long long my_add = COUNT_ONE + q;
        unsigned long long old = atomicAdd(&g_packed, my_add);
        if ((old >> COUNT_SHIFT) == (unsigned long long)(NUM_WARPS_TOTAL - 1)) {
            // last-arriving warp holds the complete packed total
            unsigned long long total = old + my_add;
            double sum = (double)(long long)(total & SUM_MASK) * INV_Q_SCALE;
            out[0] = (float)(sum / (double)BATCH);
            g_packed = 0ULL;   // reset for next graph replay (kernel-boundary ordered)
        }
    }
}

extern "C" void kernel_launch(void* const* d_in, const int* in_sizes, int n_in,
                              void* d_out, int out_size) {
    // metadata order: center_nodes, context_nodes, negative_nodes, u_weight, v_weight
    const int*   center    = (const int*)d_in[0];
    const int*   context   = (const int*)d_in[1];
    const int*   negatives = (const int*)d_in[2];
    const float* u_weight  = (const float*)d_in[3];
    const float* v_weight  = (const float*)d_in[4];
    float*       out       = (float*)d_out;

    skipgram_loss_kernel<<<NUM_BLOCKS, BLOCK_THREADS>>>(center, context, negatives,
                                                        u_weight, v_weight, out);
}

// round 14
// speedup vs baseline: 1.3459x; 1.3459x over previous
#include <cuda_runtime.h>
#include <cuda_bf16.h>
#include <math.h>

// Problem constants (fixed by the reference)
#define BATCH     65536
#define EMBED_DIM 128
#define NEG_K     5

#define WARPS_PER_BLOCK 4
#define BLOCK_THREADS   (WARPS_PER_BLOCK * 32)                 // 128
#define ELEMS_PER_WARP  2
#define NUM_BLOCKS      (BATCH / (WARPS_PER_BLOCK * ELEMS_PER_WARP))  // 8192

// Fixed-point packed accumulator+counter: low 48 bits = sum of
// round(block_sum * 2^24) [loss >= 0; total*2^24 ~ 4.6e12 << 2^48],
// bits [48:63] = arrival count (8192 max, 16-bit field). Integer adds are
// associative -> deterministic; the last-arriving block holds the complete
// total (old + own add) with no fences and no extra reads.
// NOTE: block-level (8192 atomics) is the measured optimum — R12 showed that
// per-WARP returning atomics (32768) serialize on the L2 atomic ALU and
// collapse DRAM throughput (66% -> 41%).
#define Q_SCALE     16777216.0            // 2^24
#define INV_Q_SCALE (1.0 / 16777216.0)
#define COUNT_SHIFT 48
#define COUNT_ONE   (1ULL << COUNT_SHIFT)
#define SUM_MASK    ((1ULL << COUNT_SHIFT) - 1ULL)

__device__ unsigned long long g_packed = 0ULL;

__device__ __forceinline__ float log_sigmoid(float x) {
    // stable: min(x,0) - log1p(exp(-|x|))
    return fminf(x, 0.0f) - log1pf(__expf(-fabsf(x)));
}

__device__ __forceinline__ float dot4(float4 a, float4 b) {
    return a.x * b.x + a.y * b.y + a.z * b.z + a.w * b.w;
}

__global__ __launch_bounds__(BLOCK_THREADS, 5)   // regs ~63: 14 live float4, no spills
void skipgram_loss_kernel(const int* __restrict__ center,
                          const int* __restrict__ context,
                          const int* __restrict__ negatives,
                          const float* __restrict__ u_weight,
                          const float* __restrict__ v_weight,
                          float* __restrict__ out) {
    const int warp_in_block = threadIdx.x >> 5;
    const int lane          = threadIdx.x & 31;
    const int wg            = blockIdx.x * WARPS_PER_BLOCK + warp_in_block;
    const int b0            = wg * ELEMS_PER_WARP;   // even -> negatives base is 8B-aligned

    // ---- gather indices for both elements (vectorized negatives: 5x int2) ----
    const int ci0 = center[b0],  ci1 = center[b0 + 1];
    const int xi0 = context[b0], xi1 = context[b0 + 1];
    const int2* nv = reinterpret_cast<const int2*>(negatives + (size_t)b0 * NEG_K);
    int2 q0 = __ldg(nv + 0), q1 = __ldg(nv + 1), q2 = __ldg(nv + 2),
         q3 = __ldg(nv + 3), q4 = __ldg(nv + 4);
    const int n0[NEG_K] = { q0.x, q0.y, q1.x, q1.y, q2.x };
    const int n1[NEG_K] = { q2.y, q3.x, q3.y, q4.x, q4.y };

    // ---- issue all 14 row loads back-to-back (MLP=14 per lane) ----
    const float4* c0p = reinterpret_cast<const float4*>(u_weight + (size_t)ci0 * EMBED_DIM);
    const float4* c1p = reinterpret_cast<const float4*>(u_weight + (size_t)ci1 * EMBED_DIM);
    const float4* x0p = reinterpret_cast<const float4*>(v_weight + (size_t)xi0 * EMBED_DIM);
    const float4* x1p = reinterpret_cast<const float4*>(v_weight + (size_t)xi1 * EMBED_DIM);
    float4 c40 = __ldg(c0p + lane);
    float4 c41 = __ldg(c1p + lane);
    float4 x40 = __ldg(x0p + lane);
    float4 x41 = __ldg(x1p + lane);
    float4 n40[NEG_K], n41[NEG_K];
#pragma unroll
    for (int k = 0; k < NEG_K; k++) {
        n40[k] = __ldg(reinterpret_cast<const float4*>(v_weight + (size_t)n0[k] * EMBED_DIM) + lane);
    }
#pragma unroll
    for (int k = 0; k < NEG_K; k++) {
        n41[k] = __ldg(reinterpret_cast<const float4*>(v_weight + (size_t)n1[k] * EMBED_DIM) + lane);
    }

    // ---- 12 partial dot products per lane ----
    float acc0[1 + NEG_K], acc1[1 + NEG_K];
    acc0[0] = dot4(c40, x40);
    acc1[0] = dot4(c41, x41);
#pragma unroll
    for (int k = 0; k < NEG_K; k++) {
        acc0[1 + k] = dot4(c40, n40[k]);
        acc1[1 + k] = dot4(c41, n41[k]);
    }

    // ---- butterfly warp reduction of all 12 dots (ILP across accumulators) ----
#pragma unroll
    for (int off = 16; off > 0; off >>= 1) {
#pragma unroll
        for (int j = 0; j < 1 + NEG_K; j++) {
            acc0[j] += __shfl_xor_sync(0xFFFFFFFFu, acc0[j], off);
            acc1[j] += __shfl_xor_sync(0xFFFFFFFFu, acc1[j], off);
        }
    }

    // ---- per-element losses: lane 0 handles elem0, lane 1 handles elem1 ----
    float l = 0.0f;
    if (lane == 0) {
        float neg_loss = 0.0f;
#pragma unroll
        for (int k = 0; k < NEG_K; k++) neg_loss += log_sigmoid(-acc0[1 + k]);
        l = -(log_sigmoid(acc0[0]) + neg_loss);
    } else if (lane == 1) {
        float neg_loss = 0.0f;
#pragma unroll
        for (int k = 0; k < NEG_K; k++) neg_loss += log_sigmoid(-acc1[1 + k]);
        l = -(log_sigmoid(acc1[0]) + neg_loss);
    }
    l += __shfl_xor_sync(0xFFFFFFFFu, l, 1);   // lane 0 now has loss0 + loss1

    __shared__ float smem[WARPS_PER_BLOCK];
    if (lane == 0) smem[warp_in_block] = l;
    __syncthreads();

    // ---- block reduction (fixed-order float) + single packed atomic ----
    if (threadIdx.x == 0) {
        float s = 0.0f;
#pragma unroll
        for (int w = 0; w < WARPS_PER_BLOCK; w++) s += smem[w];
        unsigned long long q = (unsigned long long)__double2ll_rn((double)s * Q_SCALE);
        unsigned long long my_add = COUNT_ONE + q;
        unsigned long long old = atomicAdd(&g_packed, my_add);
        if ((old >> COUNT_SHIFT) == (unsigned long long)(NUM_BLOCKS - 1)) {
            unsigned long long total = old + my_add;
            double sum = (double)(long long)(total & SUM_MASK) * INV_Q_SCALE;
            out[0] = (float)(sum / (double)BATCH);
            g_packed = 0ULL;   // reset for next graph replay (kernel-boundary ordered)
        }
    }
}

extern "C" void kernel_launch(void* const* d_in, const int* in_sizes, int n_in,
                              void* d_out, int out_size) {
    // metadata order: center_nodes, context_nodes, negative_nodes, u_weight, v_weight
    const int*   center    = (const int*)d_in[0];
    const int*   context   = (const int*)d_in[1];
    const int*   negatives = (const int*)d_in[2];
    const float* u_weight  = (const float*)d_in[3];
    const float* v_weight  = (const float*)d_in[4];
    float*       out       = (float*)d_out;

    skipgram_loss_kernel<<<NUM_BLOCKS, BLOCK_THREADS>>>(center, context, negatives,
                                                        u_weight, v_weight, out);
}

// round 16
// speedup vs baseline: 1.3481x; 1.0016x over previous
#include <cuda_runtime.h>
#include <cuda_bf16.h>
#include <math.h>

// Problem constants (fixed by the reference)
#define BATCH     65536
#define EMBED_DIM 128
#define NEG_K     5

#define WARPS_PER_BLOCK 4
#define BLOCK_THREADS   (WARPS_PER_BLOCK * 32)                 // 128
#define ELEMS_PER_WARP  2
#define NUM_BLOCKS      (BATCH / (WARPS_PER_BLOCK * ELEMS_PER_WARP))  // 8192

// Fixed-point packed accumulator+counter: low 48 bits = sum of
// round(block_sum * 2^24) [loss >= 0; total*2^24 ~ 4.6e12 << 2^48],
// bits [48:63] = arrival count (8192 max, 16-bit field). Integer adds are
// associative -> deterministic; the last-arriving block holds the complete
// total (old + own add) with no fences and no extra reads.
// Block-level (8192 atomics) is the measured optimum: per-warp returning
// atomics (32768, R12) serialize on the L2 atomic ALU and collapse DRAM
// throughput 66% -> 41%.
#define Q_SCALE     16777216.0            // 2^24
#define INV_Q_SCALE (1.0 / 16777216.0)
#define COUNT_SHIFT 48
#define COUNT_ONE   (1ULL << COUNT_SHIFT)
#define SUM_MASK    ((1ULL << COUNT_SHIFT) - 1ULL)

__device__ unsigned long long g_packed = 0ULL;

__device__ __forceinline__ float log_sigmoid(float x) {
    // stable: min(x,0) - log1p(exp(-|x|))
    return fminf(x, 0.0f) - log1pf(__expf(-fabsf(x)));
}

__device__ __forceinline__ float dot4(float4 a, float4 b) {
    return a.x * b.x + a.y * b.y + a.z * b.z + a.w * b.w;
}

__global__ __launch_bounds__(BLOCK_THREADS, 5)   // regs ~63: 14 live float4, no spills
void skipgram_loss_kernel(const int* __restrict__ center,
                          const int* __restrict__ context,
                          const int* __restrict__ negatives,
                          const float* __restrict__ u_weight,
                          const float* __restrict__ v_weight,
                          float* __restrict__ out) {
    const int warp_in_block = threadIdx.x >> 5;
    const int lane          = threadIdx.x & 31;
    const int wg            = blockIdx.x * WARPS_PER_BLOCK + warp_in_block;
    const int b0            = wg * ELEMS_PER_WARP;   // even -> negatives base is 8B-aligned

    // ---- gather indices for both elements (vectorized negatives: 5x int2) ----
    const int ci0 = center[b0],  ci1 = center[b0 + 1];
    const int xi0 = context[b0], xi1 = context[b0 + 1];
    const int2* nv = reinterpret_cast<const int2*>(negatives + (size_t)b0 * NEG_K);
    int2 q0 = __ldg(nv + 0), q1 = __ldg(nv + 1), q2 = __ldg(nv + 2),
         q3 = __ldg(nv + 3), q4 = __ldg(nv + 4);
    const int n0[NEG_K] = { q0.x, q0.y, q1.x, q1.y, q2.x };
    const int n1[NEG_K] = { q2.y, q3.x, q3.y, q4.x, q4.y };

    // ---- issue all 14 row loads back-to-back (MLP=14 per lane) ----
    const float4* c0p = reinterpret_cast<const float4*>(u_weight + (size_t)ci0 * EMBED_DIM);
    const float4* c1p = reinterpret_cast<const float4*>(u_weight + (size_t)ci1 * EMBED_DIM);
    const float4* x0p = reinterpret_cast<const float4*>(v_weight + (size_t)xi0 * EMBED_DIM);
    const float4* x1p = reinterpret_cast<const float4*>(v_weight + (size_t)xi1 * EMBED_DIM);
    float4 c40 = __ldg(c0p + lane);
    float4 c41 = __ldg(c1p + lane);
    float4 x40 = __ldg(x0p + lane);
    float4 x41 = __ldg(x1p + lane);
    float4 n40[NEG_K], n41[NEG_K];
#pragma unroll
    for (int k = 0; k < NEG_K; k++) {
        n40[k] = __ldg(reinterpret_cast<const float4*>(v_weight + (size_t)n0[k] * EMBED_DIM) + lane);
    }
#pragma unroll
    for (int k = 0; k < NEG_K; k++) {
        n41[k] = __ldg(reinterpret_cast<const float4*>(v_weight + (size_t)n1[k] * EMBED_DIM) + lane);
    }

    // ---- 12 partial dot products per lane ----
    float acc0[1 + NEG_K], acc1[1 + NEG_K];
    acc0[0] = dot4(c40, x40);
    acc1[0] = dot4(c41, x41);
#pragma unroll
    for (int k = 0; k < NEG_K; k++) {
        acc0[1 + k] = dot4(c40, n40[k]);
        acc1[1 + k] = dot4(c41, n41[k]);
    }

    // ---- butterfly warp reduction of all 12 dots (ILP across accumulators) ----
#pragma unroll
    for (int off = 16; off > 0; off >>= 1) {
#pragma unroll
        for (int j = 0; j < 1 + NEG_K; j++) {
            acc0[j] += __shfl_xor_sync(0xFFFFFFFFu, acc0[j], off);
            acc1[j] += __shfl_xor_sync(0xFFFFFFFFu, acc1[j], off);
        }
    }

    // ---- per-element losses: lane 0 handles elem0, lane 1 handles elem1 ----
    float l = 0.0f;
    if (lane == 0) {
        float neg_loss = 0.0f;
#pragma unroll
        for (int k = 0; k < NEG_K; k++) neg_loss += log_sigmoid(-acc0[1 + k]);
        l = -(log_sigmoid(acc0[0]) + neg_loss);
    } else if (lane == 1) {
        float neg_loss = 0.0f;
#pragma unroll
        for (int k = 0; k < NEG_K; k++) neg_loss += log_sigmoid(-acc1[1 + k]);
        l = -(log_sigmoid(acc1[0]) + neg_loss);
    }
    l += __shfl_xor_sync(0xFFFFFFFFu, l, 1);   // lane 0 now has loss0 + loss1

    __shared__ float smem[WARPS_PER_BLOCK];
    if (lane == 0) smem[warp_in_block] = l;
    __syncthreads();

    // ---- block reduction (fixed-order float) + single packed atomic ----
    if (threadIdx.x == 0) {
        float s = 0.0f;
#pragma unroll
        for (int w = 0; w < WARPS_PER_BLOCK; w++) s += smem[w];
        unsigned long long q = (unsigned long long)__double2ll_rn((double)s * Q_SCALE);
        unsigned long long my_add = COUNT_ONE + q;
        unsigned long long old = atomicAdd(&g_packed, my_add);
        if ((old >> COUNT_SHIFT) == (unsigned long long)(NUM_BLOCKS - 1)) {
            unsigned long long total = old + my_add;
            double sum = (double)(long long)(total & SUM_MASK) * INV_Q_SCALE;
            out[0] = (float)(sum / (double)BATCH);
            g_packed = 0ULL;   // reset for next graph replay (kernel-boundary ordered)
        }
    }
}

extern "C" void kernel_launch(void* const* d_in, const int* in_sizes, int n_in,
                              void* d_out, int out_size) {
    // metadata order: center_nodes, context_nodes, negative_nodes, u_weight, v_weight
    const int*   center    = (const int*)d_in[0];
    const int*   context   = (const int*)d_in[1];
    const int*   negatives = (const int*)d_in[2];
    const float* u_weight  = (const float*)d_in[3];
    const float* v_weight  = (const float*)d_in[4];
    float*       out       = (float*)d_out;

    skipgram_loss_kernel<<<NUM_BLOCKS, BLOCK_THREADS>>>(center, context, negatives,
                                                        u_weight, v_weight, out);
}